// round 1
// baseline (speedup 1.0000x reference)
#include <cuda_runtime.h>
#include <math.h>

#define Bsz 4
#define Cch 192
#define Hh 56
#define Ww 56
#define HW (Hh*Ww)
#define NS 27

// scratch (static device globals; no allocation)
__device__ float g_xt [Bsz*HW*Cch];   // x transposed to [b][n][c]  (NHWC)
__device__ float g_att[Bsz*HW*Cch];   // attention output, [b][n][c]

// ---------------------------------------------------------------------------
// Kernel 1: NCHW -> NHWC transpose (per-batch CxHW matrix transpose)
// ---------------------------------------------------------------------------
__global__ __launch_bounds__(256) void transpose_k(const float* __restrict__ x)
{
    __shared__ float tile[32][33];
    const int n0 = blockIdx.x << 5;      // HW tile (3136 = 98*32)
    const int c0 = blockIdx.y << 5;      // C tile  (192  = 6*32)
    const int b  = blockIdx.z;
    const int tx = threadIdx.x, ty = threadIdx.y;   // (32, 8)
    const float* xb = x + (size_t)b * Cch * HW;
#pragma unroll
    for (int i = 0; i < 4; i++)
        tile[ty + i*8][tx] = xb[(size_t)(c0 + ty + i*8) * HW + n0 + tx];
    __syncthreads();
    float* dst = g_xt + (size_t)b * HW * Cch;
#pragma unroll
    for (int i = 0; i < 4; i++)
        dst[(size_t)(n0 + ty + i*8) * Cch + c0 + tx] = tile[tx][ty + i*8];
}

// ---------------------------------------------------------------------------
// Kernel 2: shift-attention. One block per (b,h,w); thread = channel.
// ---------------------------------------------------------------------------
__device__ __forceinline__ float fast_tanh(float p)
{
    float a = fabsf(p);
    float e = __expf(-2.0f * a);                       // MUFU.EX2, rel err ~2^-22
    float t = __fdividef(1.0f - e, 1.0f + e);          // MUFU.RCP based
    return copysignf(t, p);
}

__global__ __launch_bounds__(192) void att_k()
{
    const int w = blockIdx.x, h = blockIdx.y, b = blockIdx.z;
    const int c = threadIdx.x;                         // 192 threads = channels
    __shared__ float ts[192 * 29];                     // per-(c,shift) tanh vals (stride 29: conflict-free)
    __shared__ float wgt[NS];
    const float scale = 0.19245008972987526f;          // 27^-0.5
    const float* base = g_xt + (size_t)b * HW * Cch;

    const float xc = base[(h*Ww + w)*Cch + c];
    float xs[NS];
#pragma unroll
    for (int i = 0; i < 14; i++) {                     // h-shifts 0,4,...,52: rolled[h] = x[(h-s) mod H]
        int hh = h - 4*i; if (hh < 0) hh += Hh;
        xs[i] = base[(hh*Ww + w)*Cch + c];
    }
#pragma unroll
    for (int j = 1; j < 14; j++) {                     // w-shifts 4,...,52
        int ww = w - 4*j; if (ww < 0) ww += Ww;
        xs[13 + j] = base[(h*Ww + ww)*Cch + c];
    }

#pragma unroll
    for (int i = 0; i < NS; i++)
        ts[c*29 + i] = fast_tanh(scale * xc * xs[i]);
    __syncthreads();

    // warp 0: reduce scores over channels, softmax over 27 shifts
    if (c < 32) {
        float s = 0.f;
        if (c < NS) {
            float s0 = 0.f, s1 = 0.f, s2 = 0.f, s3 = 0.f;
            for (int cc = 0; cc < 192; cc += 4) {
                s0 += ts[(cc+0)*29 + c];
                s1 += ts[(cc+1)*29 + c];
                s2 += ts[(cc+2)*29 + c];
                s3 += ts[(cc+3)*29 + c];
            }
            s = (s0 + s1) + (s2 + s3);
        }
        float sv = (c < NS) ? s : -1e30f;
#pragma unroll
        for (int off = 16; off; off >>= 1)
            sv = fmaxf(sv, __shfl_xor_sync(0xffffffffu, sv, off));
        float e = (c < NS) ? __expf(s - sv) : 0.f;
        float tot = e;
#pragma unroll
        for (int off = 16; off; off >>= 1)
            tot += __shfl_xor_sync(0xffffffffu, tot, off);
        if (c < NS) wgt[c] = __fdividef(e, tot);
    }
    __syncthreads();

    float o = 0.f;
#pragma unroll
    for (int i = 0; i < NS; i++) o = fmaf(wgt[i], xs[i], o);
    g_att[(size_t)b*HW*Cch + (h*Ww + w)*Cch + c] = o;
}

// ---------------------------------------------------------------------------
// Kernel 3: 1x1 conv as GEMM (M=192, N=3136/batch, K=384) + bias + BN + GELU.
// Packed f32x2 FFMA2 inner loop (2x fp32 FFMA throughput on sm_103a).
// Accumulator pairs are adjacent OUTPUT channels, so the weight operand loads
// as a native LDS.64 pair; only the 4 cat values/k need dup-packing.
// ---------------------------------------------------------------------------
#define BN 64
#define BK 32
#define WS_STRIDE 194   // even (8B-aligned 64-bit reads), 194%32=2 -> 2-way store conflict only
#define CS_STRIDE 68

__device__ __forceinline__ unsigned long long dup2(float v)
{
    unsigned long long d; unsigned r = __float_as_uint(v);
    asm("mov.b64 %0, {%1, %1};" : "=l"(d) : "r"(r));
    return d;
}
#define FFMA2(d, a, b) asm("fma.rn.f32x2 %0, %1, %2, %0;" : "+l"(d) : "l"(a), "l"(b))

__global__ __launch_bounds__(256) void gemm_k(
    const float* __restrict__ cw,    // conv_w [192][384]
    const float* __restrict__ bias,
    const float* __restrict__ gamma,
    const float* __restrict__ beta,
    const float* __restrict__ mean,
    const float* __restrict__ var,
    float* __restrict__ out)         // [b][o][n] (NCHW)
{
    __shared__ float wS[BK * WS_STRIDE];   // [k][o]  (k-major rows of 192 weights)
    __shared__ float catS[BK * CS_STRIDE]; // [k][n]
    const int b  = blockIdx.y;
    const int n0 = blockIdx.x * BN;
    const int t  = threadIdx.x;
    const int tn = t & 15;                 // 16 n-groups of 4
    const int tm = t >> 4;                 // 16 o-groups of 12

    unsigned long long acc[6][4];          // 6 o-pairs x 4 n  (= 12x4 fp32 accs)
#pragma unroll
    for (int p = 0; p < 6; p++)
#pragma unroll
        for (int nn = 0; nn < 4; nn++) acc[p][nn] = 0ULL;

    const float* xb = g_xt  + (size_t)b * HW * Cch;
    const float* ab = g_att + (size_t)b * HW * Cch;

    for (int kc = 0; kc < 2*Cch; kc += BK) {
        const float* src  = (kc < Cch) ? xb : ab;
        const int   cbase = (kc < Cch) ? kc : (kc - Cch);
        __syncthreads();
        // cat tile: 32 c x 64 n, lanes along c (coalesced in NHWC)
#pragma unroll
        for (int s = 0; s < 8; s++) {
            int f = t + 256*s;
            int cc = f & 31, j = f >> 5;
            catS[cc*CS_STRIDE + j] = src[(size_t)(n0 + j)*Cch + cbase + cc];
        }
        // weight tile: 32 c x 192 o, transposed into [k][o]
#pragma unroll
        for (int s = 0; s < 24; s++) {
            int f = t + 256*s;
            int cc = f & 31, o = f >> 5;
            wS[cc*WS_STRIDE + o] = cw[o*384 + kc + cc];
        }
        __syncthreads();
#pragma unroll
        for (int k = 0; k < BK; k++) {
            unsigned long long a[6];
#pragma unroll
            for (int p = 0; p < 6; p++)
                a[p] = *reinterpret_cast<const unsigned long long*>(
                           &wS[k*WS_STRIDE + tm*12 + 2*p]);
            unsigned long long bb[4];
#pragma unroll
            for (int nn = 0; nn < 4; nn++)
                bb[nn] = dup2(catS[k*CS_STRIDE + tn*4 + nn]);
#pragma unroll
            for (int p = 0; p < 6; p++)
#pragma unroll
                for (int nn = 0; nn < 4; nn++)
                    FFMA2(acc[p][nn], a[p], bb[nn]);
        }
    }

    // epilogue: bias + BN(eval) + exact GELU, vectorized stores
#pragma unroll
    for (int p = 0; p < 6; p++) {
        float yv[2][4];
#pragma unroll
        for (int nn = 0; nn < 4; nn++) {
            unsigned long long v = acc[p][nn];
            yv[0][nn] = __uint_as_float((unsigned)v);
            yv[1][nn] = __uint_as_float((unsigned)(v >> 32));
        }
#pragma unroll
        for (int q = 0; q < 2; q++) {
            int o = tm*12 + 2*p + q;
            float bi  = bias[o];
            float inv = gamma[o] * rsqrtf(var[o] + 1e-5f);
            float mu  = mean[o], bt = beta[o];
            float4 r;
            float* rp = &r.x;
#pragma unroll
            for (int nn = 0; nn < 4; nn++) {
                float y = (yv[q][nn] + bi - mu) * inv + bt;
                rp[nn] = 0.5f * y * (1.0f + erff(y * 0.70710678118654752f));
            }
            *reinterpret_cast<float4*>(
                &out[(size_t)(b*Cch + o)*HW + n0 + tn*4]) = r;
        }
    }
}

// ---------------------------------------------------------------------------
extern "C" void kernel_launch(void* const* d_in, const int* in_sizes, int n_in,
                              void* d_out, int out_size)
{
    const float* x     = (const float*)d_in[0];
    const float* cw    = (const float*)d_in[1];
    const float* cb    = (const float*)d_in[2];
    const float* gamma = (const float*)d_in[3];
    const float* beta  = (const float*)d_in[4];
    const float* mean  = (const float*)d_in[5];
    const float* var   = (const float*)d_in[6];
    float* out = (float*)d_out;

    transpose_k<<<dim3(HW/32, Cch/32, Bsz), dim3(32, 8)>>>(x);
    att_k<<<dim3(Ww, Hh, Bsz), 192>>>();
    gemm_k<<<dim3(HW/BN, Bsz), 256>>>(cw, cb, gamma, beta, mean, var, out);
}